// round 4
// baseline (speedup 1.0000x reference)
#include <cuda_runtime.h>
#include <cuda_bf16.h>
#include <stdint.h>

#define B_ 4096
#define L_ 200
#define E_ 128
#define F_ 64
#define LDF 72
#define LDK 136
#define PREP_SMEM ((32*128 + 2*128*132)*4)

__device__ __align__(16) __nv_bfloat16 g_w1f[E_*LDF];
__device__ __align__(16) __nv_bfloat16 g_w2f[E_*LDK];
__device__ __align__(16) __nv_bfloat16 g_w1i[E_*LDK];
__device__ __align__(16) __nv_bfloat16 g_w1c[E_*LDK];
__device__ float g_cu[B_*E_];
__device__ float g_c2u[B_*E_];

__global__ void pack_weights(const float* __restrict__ fw1,
                             const float* __restrict__ fw2,
                             const float* __restrict__ w1) {
    int i = blockIdx.x * blockDim.x + threadIdx.x;
    if (i < 128*64) {
        int n = i >> 6, k = i & 63;
        g_w1f[n*LDF + k] = __float2bfloat16_rn(fw1[n*192 + 128 + k]);
        return;
    }
    i -= 128*64;
    if (i < 128*128) {
        int n = i >> 7, k = i & 127;
        g_w2f[n*LDK + k] = __float2bfloat16_rn(fw2[n*128 + k]);
        return;
    }
    i -= 128*128;
    if (i < 128*128) {
        int n = i >> 7, k = i & 127;
        g_w1i[n*LDK + k] = __float2bfloat16_rn(w1[n*384 + 128 + k]);
        return;
    }
    i -= 128*128;
    if (i < 128*128) {
        int n = i >> 7, k = i & 127;
        g_w1c[n*LDK + k] = __float2bfloat16_rn(w1[n*384 + 256 + k]);
    }
}

// 128 CTAs x 256 thr, 32 batch rows each: g_cu = fb1 + user@fw1[:,:128]^T, g_c2u = b1 + user@w1[:,:128]^T
__global__ void __launch_bounds__(256) prep_user(
    const int* __restrict__ user_ids, const float* __restrict__ user_emb,
    const float* __restrict__ fw1, const float* __restrict__ w1,
    const float* __restrict__ fb1, const float* __restrict__ b1v) {
    extern __shared__ float sm[];
    float* su  = sm;               // [32][128]
    float* wt1 = sm + 32*128;      // [f=128][132]
    float* wt2 = wt1 + 128*132;
    const int tid = threadIdx.x;
    const int b0 = blockIdx.x * 32;
    for (int i = tid; i < 32*128; i += 256) {
        int bl = i >> 7, f = i & 127;
        su[i] = user_emb[(size_t)user_ids[b0 + bl] * E_ + f];
    }
    for (int i = tid; i < 128*128; i += 256) {
        int n = i >> 7, f = i & 127;
        wt1[f*132 + n] = fw1[n*192 + f];
        wt2[f*132 + n] = w1[n*384 + f];
    }
    __syncthreads();
    const int m = tid >> 7, n = tid & 127;
    const float* wt = m ? wt2 : wt1;
    const float bias = m ? b1v[n] : fb1[n];
    float* gout = m ? g_c2u : g_cu;
    for (int bl = 0; bl < 32; bl++) {
        float acc = bias;
        const float* u = su + bl*128;
        #pragma unroll 8
        for (int f = 0; f < 128; f++) acc += u[f] * wt[f*132 + n];
        gout[(size_t)(b0 + bl) * E_ + n] = acc;
    }
}

struct __align__(16) SmemMain {
    __nv_bfloat16 w1f[E_*LDF];
    __nv_bfloat16 w2f[E_*LDK];
    __nv_bfloat16 w1i[E_*LDK];
    __nv_bfloat16 w1c[E_*LDK];
    __nv_bfloat16 feat[64*LDF];
    __nv_bfloat16 items[64*LDK];
    __nv_bfloat16 fx[64*LDK];
    __nv_bfloat16 comp[64*LDK];
    float user[E_];
    float cu[E_];
    float c2u[E_];
    float fb2[E_];
    float w2v[E_];
    float part[4][64];
    float logits[256];
    float red[8];
    float scal[2];
    int   ids[L_];
};

__device__ __forceinline__ void copyw(void* dst, const void* src, int bytes, int tid) {
    uint4* d = (uint4*)dst;
    const uint4* s = (const uint4*)src;
    const int n = bytes >> 4;
    for (int i = tid; i < n; i += 256) d[i] = s[i];
}

__device__ __forceinline__ void mma16816(float* d, const uint32_t* a, const uint32_t* b) {
    asm volatile(
        "mma.sync.aligned.m16n8k16.row.col.f32.bf16.bf16.f32 "
        "{%0,%1,%2,%3},{%4,%5,%6,%7},{%8,%9},{%0,%1,%2,%3};\n"
        : "+f"(d[0]), "+f"(d[1]), "+f"(d[2]), "+f"(d[3])
        : "r"(a[0]), "r"(a[1]), "r"(a[2]), "r"(a[3]), "r"(b[0]), "r"(b[1]));
}

// A pre-offset to (m_base+g)*lda + t4*2; Bm pre-offset to (n_base+g)*ldb + t4*2
template<int NK>
__device__ __forceinline__ void gemm_tile(const __nv_bfloat16* __restrict__ A, int lda,
                                          const __nv_bfloat16* __restrict__ Bm, int ldb,
                                          float acc[2][4][4]) {
    #pragma unroll
    for (int ks = 0; ks < NK; ks++) {
        const int k0 = ks * 16;
        uint32_t a[2][4];
        #pragma unroll
        for (int t = 0; t < 2; t++) {
            const __nv_bfloat16* p = A + t*16*lda + k0;
            a[t][0] = *(const uint32_t*)(p);
            a[t][1] = *(const uint32_t*)(p + 8*lda);
            a[t][2] = *(const uint32_t*)(p + 8);
            a[t][3] = *(const uint32_t*)(p + 8*lda + 8);
        }
        #pragma unroll
        for (int j = 0; j < 4; j++) {
            const __nv_bfloat16* q = Bm + j*8*ldb + k0;
            uint32_t bb[2];
            bb[0] = *(const uint32_t*)(q);
            bb[1] = *(const uint32_t*)(q + 8);
            mma16816(acc[0][j], a[0], bb);
            mma16816(acc[1][j], a[1], bb);
        }
    }
}

__device__ __forceinline__ void zero_acc(float acc[2][4][4]) {
    #pragma unroll
    for (int t = 0; t < 2; t++)
        #pragma unroll
        for (int j = 0; j < 4; j++)
            #pragma unroll
            for (int i = 0; i < 4; i++) acc[t][j][i] = 0.f;
}

__device__ __forceinline__ void epi_store(const float acc[2][4][4],
                                          const float* __restrict__ addv,
                                          __nv_bfloat16* __restrict__ sOut, int ldo,
                                          int wm, int wn, int g, int t4) {
    #pragma unroll
    for (int t = 0; t < 2; t++) {
        const int r0 = wm*32 + t*16 + g;
        #pragma unroll
        for (int j = 0; j < 4; j++) {
            const int c = wn*32 + j*8 + t4*2;
            const float a0 = addv[c], a1 = addv[c+1];
            __nv_bfloat162 v01 = __floats2bfloat162_rn(fmaxf(acc[t][j][0] + a0, 0.f),
                                                       fmaxf(acc[t][j][1] + a1, 0.f));
            __nv_bfloat162 v23 = __floats2bfloat162_rn(fmaxf(acc[t][j][2] + a0, 0.f),
                                                       fmaxf(acc[t][j][3] + a1, 0.f));
            *(__nv_bfloat162*)(sOut + r0*ldo + c) = v01;
            *(__nv_bfloat162*)(sOut + (r0+8)*ldo + c) = v23;
        }
    }
}

__device__ __forceinline__ float block_reduce(float v, bool do_max, SmemMain* s, int tid) {
    #pragma unroll
    for (int o = 16; o > 0; o >>= 1) {
        float u = __shfl_xor_sync(0xffffffffu, v, o);
        v = do_max ? fmaxf(v, u) : (v + u);
    }
    if ((tid & 31) == 0) s->red[tid >> 5] = v;
    __syncthreads();
    if (tid == 0) {
        float r = s->red[0];
        #pragma unroll
        for (int i = 1; i < 8; i++) r = do_max ? fmaxf(r, s->red[i]) : (r + s->red[i]);
        s->scal[0] = r;
    }
    __syncthreads();
    return s->scal[0];
}

__global__ void __launch_bounds__(256, 1) main_kernel(
    const int* __restrict__ user_ids, const int* __restrict__ item_ids,
    const float* __restrict__ features, const float* __restrict__ user_emb,
    const float* __restrict__ item_emb, const float* __restrict__ feat_b2,
    const float* __restrict__ w2, const float* __restrict__ b2,
    float* __restrict__ out) {
    extern __shared__ char smraw[];
    SmemMain* s = (SmemMain*)smraw;
    const int tid = threadIdx.x;
    const int lane = tid & 31, wid = tid >> 5;
    const int wm = wid & 1, wn = wid >> 1;
    const int g = lane >> 2, t4 = lane & 3;

    copyw(s->w1f, g_w1f, (int)sizeof(g_w1f), tid);
    copyw(s->w2f, g_w2f, (int)sizeof(g_w2f), tid);
    copyw(s->w1i, g_w1i, (int)sizeof(g_w1i), tid);
    copyw(s->w1c, g_w1c, (int)sizeof(g_w1c), tid);
    if (tid < E_) { s->fb2[tid] = feat_b2[tid]; s->w2v[tid] = w2[tid]; }
    const float b2v = b2[0];

    for (int b = blockIdx.x; b < B_; b += gridDim.x) {
        __syncthreads();
        if (tid < E_) {
            s->user[tid] = user_emb[(size_t)user_ids[b] * E_ + tid];
            s->cu[tid]   = g_cu[(size_t)b * E_ + tid];
            s->c2u[tid]  = g_c2u[(size_t)b * E_ + tid];
        }
        if (tid < L_) s->ids[tid] = item_ids[b*L_ + tid];

        for (int tile = 0; tile < 4; tile++) {
            __syncthreads();
            const int base = tile * 64;
            for (int i = tid; i < 64*16; i += 256) {
                int r = i >> 4, q = i & 15;
                int l = base + r;
                float4 v = make_float4(0.f, 0.f, 0.f, 0.f);
                if (l < L_)
                    v = ((const float4*)features)[(size_t)(b*L_ + l)*16 + q];
                __nv_bfloat162* dst = (__nv_bfloat162*)(s->feat + r*LDF + q*4);
                dst[0] = __floats2bfloat162_rn(v.x, v.y);
                dst[1] = __floats2bfloat162_rn(v.z, v.w);
            }
            for (int i = tid; i < 64*32; i += 256) {
                int r = i >> 5, q = i & 31;
                int l = base + r;
                float4 v = make_float4(0.f, 0.f, 0.f, 0.f);
                if (l < L_)
                    v = ((const float4*)item_emb)[(size_t)s->ids[l]*32 + q];
                __nv_bfloat162* dst = (__nv_bfloat162*)(s->items + r*LDK + q*4);
                dst[0] = __floats2bfloat162_rn(v.x, v.y);
                dst[1] = __floats2bfloat162_rn(v.z, v.w);
            }
            __syncthreads();

            float acc[2][4][4];
            // fx = relu(cu + feat @ w1f^T)
            zero_acc(acc);
            gemm_tile<4>(s->feat + (wm*32 + g)*LDF + t4*2, LDF,
                         s->w1f  + (wn*32 + g)*LDF + t4*2, LDF, acc);
            epi_store(acc, s->cu, s->fx, LDK, wm, wn, g, t4);
            __syncthreads();

            // comp = relu(fb2 + fx @ w2f^T)
            zero_acc(acc);
            gemm_tile<8>(s->fx  + (wm*32 + g)*LDK + t4*2, LDK,
                         s->w2f + (wn*32 + g)*LDK + t4*2, LDK, acc);
            epi_store(acc, s->fb2, s->comp, LDK, wm, wn, g, t4);
            __syncthreads();

            // h = relu(c2u + items@w1i^T + comp@w1c^T); logit = w2.h (+b2)
            zero_acc(acc);
            gemm_tile<8>(s->items + (wm*32 + g)*LDK + t4*2, LDK,
                         s->w1i   + (wn*32 + g)*LDK + t4*2, LDK, acc);
            gemm_tile<8>(s->comp  + (wm*32 + g)*LDK + t4*2, LDK,
                         s->w1c   + (wn*32 + g)*LDK + t4*2, LDK, acc);
            #pragma unroll
            for (int t = 0; t < 2; t++) {
                float p0 = 0.f, p1 = 0.f;
                #pragma unroll
                for (int j = 0; j < 4; j++) {
                    const int c = wn*32 + j*8 + t4*2;
                    const float a0 = s->c2u[c], a1 = s->c2u[c+1];
                    const float q0 = s->w2v[c], q1 = s->w2v[c+1];
                    p0 += fmaxf(acc[t][j][0] + a0, 0.f)*q0 + fmaxf(acc[t][j][1] + a1, 0.f)*q1;
                    p1 += fmaxf(acc[t][j][2] + a0, 0.f)*q0 + fmaxf(acc[t][j][3] + a1, 0.f)*q1;
                }
                p0 += __shfl_xor_sync(0xffffffffu, p0, 1);
                p0 += __shfl_xor_sync(0xffffffffu, p0, 2);
                p1 += __shfl_xor_sync(0xffffffffu, p1, 1);
                p1 += __shfl_xor_sync(0xffffffffu, p1, 2);
                if (t4 == 0) {
                    const int r = wm*32 + t*16 + g;
                    s->part[wn][r]     = p0;
                    s->part[wn][r + 8] = p1;
                }
            }
            __syncthreads();
            if (tid < 64)
                s->logits[base + tid] = b2v + s->part[0][tid] + s->part[1][tid]
                                            + s->part[2][tid] + s->part[3][tid];
        }
        __syncthreads();

        float mv = -3.4e38f;
        for (int i = tid; i < L_; i += 256) mv = fmaxf(mv, s->logits[i]);
        mv = block_reduce(mv, true, s, tid);
        float sv = 0.f;
        for (int i = tid; i < L_; i += 256) {
            float e = __expf(s->logits[i] - mv);
            s->logits[i] = e;
            sv += e;
        }
        sv = block_reduce(sv, false, s, tid);
        const float inv = 1.f / sv;

        const int e = tid & 127, half = tid >> 7;
        float accv = 0.f;
        for (int l = half; l < L_; l += 2)
            accv += s->logits[l] * __ldg(item_emb + (size_t)s->ids[l]*E_ + e);
        float* pbuf = &s->part[0][0];
        if (half) pbuf[e] = accv;
        __syncthreads();
        if (!half)
            out[(size_t)b*E_ + e] = s->user[e] + (accv + pbuf[e]) * inv;
    }
}

extern "C" void kernel_launch(void* const* d_in, const int* in_sizes, int n_in,
                              void* d_out, int out_size) {
    const int*   user_ids = (const int*)d_in[0];
    const int*   item_ids = (const int*)d_in[1];
    const float* features = (const float*)d_in[2];
    const float* user_emb = (const float*)d_in[3];
    const float* item_emb = (const float*)d_in[4];
    const float* feat_w1  = (const float*)d_in[5];
    const float* feat_b1  = (const float*)d_in[6];
    const float* feat_w2  = (const float*)d_in[7];
    const float* feat_b2  = (const float*)d_in[8];
    const float* w1       = (const float*)d_in[9];
    const float* b1       = (const float*)d_in[10];
    const float* w2       = (const float*)d_in[11];
    const float* b2       = (const float*)d_in[12];
    float* out = (float*)d_out;

    cudaFuncSetAttribute(prep_user, cudaFuncAttributeMaxDynamicSharedMemorySize, PREP_SMEM);
    cudaFuncSetAttribute(main_kernel, cudaFuncAttributeMaxDynamicSharedMemorySize,
                         (int)sizeof(SmemMain));
    int nsm = 148;
    cudaDeviceGetAttribute(&nsm, cudaDevAttrMultiProcessorCount, 0);

    pack_weights<<<224, 256>>>(feat_w1, feat_w2, w1);
    prep_user<<<128, 256, PREP_SMEM>>>(user_ids, user_emb, feat_w1, w1, feat_b1, b1);
    main_kernel<<<nsm, 256, sizeof(SmemMain)>>>(user_ids, item_ids, features, user_emb,
                                                item_emb, feat_b2, w2, b2, out);
}

// round 5
// speedup vs baseline: 1.6301x; 1.6301x over previous
#include <cuda_runtime.h>
#include <cuda_bf16.h>
#include <stdint.h>

#define B_ 4096
#define L_ 200
#define E_ 128
#define F_ 64
#define LDF 72
#define LDK 136
#define PREP_SMEM ((32*128 + 2*128*132)*4)

__device__ __align__(16) __nv_bfloat16 g_w1f[E_*LDF];
__device__ __align__(16) __nv_bfloat16 g_w2f[E_*LDK];
__device__ __align__(16) __nv_bfloat16 g_w1i[E_*LDK];
__device__ __align__(16) __nv_bfloat16 g_w1c[E_*LDK];
__device__ float g_cu[B_*E_];
__device__ float g_c2u[B_*E_];

// 128 CTAs x 256 thr. Also packs all bf16 weights (folded former pack_weights).
__global__ void __launch_bounds__(256) prep_user(
    const int* __restrict__ user_ids, const float* __restrict__ user_emb,
    const float* __restrict__ fw1, const float* __restrict__ fw2,
    const float* __restrict__ w1,
    const float* __restrict__ fb1, const float* __restrict__ b1v) {
    extern __shared__ float sm[];
    float* su  = sm;               // [32][128]
    float* wt1 = sm + 32*128;      // [f=128][132]
    float* wt2 = wt1 + 128*132;
    const int tid = threadIdx.x;
    const int b0 = blockIdx.x * 32;

    // ---- weight packing (independent of smem/sync) ----
    for (int j = blockIdx.x*256 + tid; j < 128*64 + 3*128*128; j += 128*256) {
        int i = j;
        if (i < 128*64) {
            int n = i >> 6, k = i & 63;
            g_w1f[n*LDF + k] = __float2bfloat16_rn(fw1[n*192 + 128 + k]);
            continue;
        }
        i -= 128*64;
        if (i < 128*128) {
            int n = i >> 7, k = i & 127;
            g_w2f[n*LDK + k] = __float2bfloat16_rn(fw2[n*128 + k]);
            continue;
        }
        i -= 128*128;
        if (i < 128*128) {
            int n = i >> 7, k = i & 127;
            g_w1i[n*LDK + k] = __float2bfloat16_rn(w1[n*384 + 128 + k]);
            continue;
        }
        i -= 128*128;
        {
            int n = i >> 7, k = i & 127;
            g_w1c[n*LDK + k] = __float2bfloat16_rn(w1[n*384 + 256 + k]);
        }
    }

    for (int i = tid; i < 32*128; i += 256) {
        int bl = i >> 7, f = i & 127;
        su[i] = user_emb[(size_t)user_ids[b0 + bl] * E_ + f];
    }
    for (int i = tid; i < 128*128; i += 256) {
        int n = i >> 7, f = i & 127;
        wt1[f*132 + n] = fw1[n*192 + f];
        wt2[f*132 + n] = w1[n*384 + f];
    }
    __syncthreads();
    const int m = tid >> 7, n = tid & 127;
    const float* wt = m ? wt2 : wt1;
    const float bias = m ? b1v[n] : fb1[n];
    float* gout = m ? g_c2u : g_cu;
    for (int bl = 0; bl < 32; bl++) {
        float acc = bias;
        const float* u = su + bl*128;
        #pragma unroll 8
        for (int f = 0; f < 128; f++) acc += u[f] * wt[f*132 + n];
        gout[(size_t)(b0 + bl) * E_ + n] = acc;
    }
}

struct __align__(16) SmemMain {
    __nv_bfloat16 w1f[E_*LDF];
    __nv_bfloat16 w2f[E_*LDK];
    __nv_bfloat16 w1i[E_*LDK];
    __nv_bfloat16 w1c[E_*LDK];
    __nv_bfloat16 feat[64*LDF];
    __nv_bfloat16 items[64*LDK];
    __nv_bfloat16 fx[64*LDK];
    __nv_bfloat16 comp[64*LDK];
    float user[E_];
    float cu[E_];
    float c2u[E_];
    float fb2[E_];
    float w2v[E_];
    float part[4][64];
    float logits[256];
    float red[8];
    float scal[2];
    int   ids[L_];
};

__device__ __forceinline__ void copyw(void* dst, const void* src, int bytes, int tid) {
    uint4* d = (uint4*)dst;
    const uint4* s = (const uint4*)src;
    const int n = bytes >> 4;
    for (int i = tid; i < n; i += 256) d[i] = s[i];
}

__device__ __forceinline__ uint32_t su32(const void* p) {
    return (uint32_t)__cvta_generic_to_shared(p);
}

__device__ __forceinline__ void ldsm4(uint32_t r[4], uint32_t a) {
    asm volatile("ldmatrix.sync.aligned.m8n8.x4.shared.b16 {%0,%1,%2,%3},[%4];"
        : "=r"(r[0]), "=r"(r[1]), "=r"(r[2]), "=r"(r[3]) : "r"(a));
}

__device__ __forceinline__ void mma16816(float* d, const uint32_t* a, const uint32_t* b) {
    asm volatile(
        "mma.sync.aligned.m16n8k16.row.col.f32.bf16.bf16.f32 "
        "{%0,%1,%2,%3},{%4,%5,%6,%7},{%8,%9},{%0,%1,%2,%3};\n"
        : "+f"(d[0]), "+f"(d[1]), "+f"(d[2]), "+f"(d[3])
        : "r"(a[0]), "r"(a[1]), "r"(a[2]), "r"(a[3]), "r"(b[0]), "r"(b[1]));
}

// aB: smem byte addr of A + (m_base + (lane&15))*lda2 + (lane>>4)*16
// bB: smem byte addr of B + (n_base + (lane&15))*ldb2 + (lane>>4)*16
// lda2/ldb2 are row strides in BYTES. Advances 32B (16 bf16) per k-slice.
template<int NK>
__device__ __forceinline__ void gemm_lm(uint32_t aB, int lda2, uint32_t bB, int ldb2,
                                        float acc[2][4][4]) {
    #pragma unroll
    for (int ks = 0; ks < NK; ks++) {
        uint32_t a0[4], a1[4], p[4], q[4];
        ldsm4(a0, aB + ks*32);
        ldsm4(a1, aB + 16*lda2 + ks*32);
        ldsm4(p,  bB + ks*32);
        ldsm4(q,  bB + 16*ldb2 + ks*32);
        uint32_t bj[4][2] = {{p[0], p[2]}, {p[1], p[3]}, {q[0], q[2]}, {q[1], q[3]}};
        #pragma unroll
        for (int j = 0; j < 4; j++) {
            mma16816(acc[0][j], a0, bj[j]);
            mma16816(acc[1][j], a1, bj[j]);
        }
    }
}

__device__ __forceinline__ void zero_acc(float acc[2][4][4]) {
    #pragma unroll
    for (int t = 0; t < 2; t++)
        #pragma unroll
        for (int j = 0; j < 4; j++)
            #pragma unroll
            for (int i = 0; i < 4; i++) acc[t][j][i] = 0.f;
}

__device__ __forceinline__ void epi_store(const float acc[2][4][4],
                                          const float* __restrict__ addv,
                                          __nv_bfloat16* __restrict__ sOut, int ldo,
                                          int wm, int wn, int g, int t4) {
    #pragma unroll
    for (int t = 0; t < 2; t++) {
        const int r0 = wm*32 + t*16 + g;
        #pragma unroll
        for (int j = 0; j < 4; j++) {
            const int c = wn*32 + j*8 + t4*2;
            const float a0 = addv[c], a1 = addv[c+1];
            __nv_bfloat162 v01 = __floats2bfloat162_rn(fmaxf(acc[t][j][0] + a0, 0.f),
                                                       fmaxf(acc[t][j][1] + a1, 0.f));
            __nv_bfloat162 v23 = __floats2bfloat162_rn(fmaxf(acc[t][j][2] + a0, 0.f),
                                                       fmaxf(acc[t][j][3] + a1, 0.f));
            *(__nv_bfloat162*)(sOut + r0*ldo + c) = v01;
            *(__nv_bfloat162*)(sOut + (r0+8)*ldo + c) = v23;
        }
    }
}

__device__ __forceinline__ float block_reduce(float v, bool do_max, SmemMain* s, int tid) {
    #pragma unroll
    for (int o = 16; o > 0; o >>= 1) {
        float u = __shfl_xor_sync(0xffffffffu, v, o);
        v = do_max ? fmaxf(v, u) : (v + u);
    }
    if ((tid & 31) == 0) s->red[tid >> 5] = v;
    __syncthreads();
    if (tid == 0) {
        float r = s->red[0];
        #pragma unroll
        for (int i = 1; i < 8; i++) r = do_max ? fmaxf(r, s->red[i]) : (r + s->red[i]);
        s->scal[0] = r;
    }
    __syncthreads();
    return s->scal[0];
}

__global__ void __launch_bounds__(256, 1) main_kernel(
    const int* __restrict__ user_ids, const int* __restrict__ item_ids,
    const float* __restrict__ features, const float* __restrict__ user_emb,
    const float* __restrict__ item_emb, const float* __restrict__ feat_b2,
    const float* __restrict__ w2, const float* __restrict__ b2,
    float* __restrict__ out) {
    extern __shared__ char smraw[];
    SmemMain* s = (SmemMain*)smraw;
    const int tid = threadIdx.x;
    const int lane = tid & 31, wid = tid >> 5;
    const int wm = wid & 1, wn = wid >> 1;
    const int g = lane >> 2, t4 = lane & 3;
    const int rl = lane & 15, hk = lane >> 4;   // ldmatrix row-lane / k-half

    copyw(s->w1f, g_w1f, (int)sizeof(g_w1f), tid);
    copyw(s->w2f, g_w2f, (int)sizeof(g_w2f), tid);
    copyw(s->w1i, g_w1i, (int)sizeof(g_w1i), tid);
    copyw(s->w1c, g_w1c, (int)sizeof(g_w1c), tid);
    if (tid < E_) { s->fb2[tid] = feat_b2[tid]; s->w2v[tid] = w2[tid]; }
    const float b2v = b2[0];

    // ldmatrix base addresses (byte offsets advance per-GEMM)
    const uint32_t aF = su32(s->feat)  + (wm*32 + rl)*(LDF*2) + hk*16;
    const uint32_t bF = su32(s->w1f)   + (wn*32 + rl)*(LDF*2) + hk*16;
    const uint32_t aX = su32(s->fx)    + (wm*32 + rl)*(LDK*2) + hk*16;
    const uint32_t b2f= su32(s->w2f)   + (wn*32 + rl)*(LDK*2) + hk*16;
    const uint32_t aI = su32(s->items) + (wm*32 + rl)*(LDK*2) + hk*16;
    const uint32_t bI = su32(s->w1i)   + (wn*32 + rl)*(LDK*2) + hk*16;
    const uint32_t aC = su32(s->comp)  + (wm*32 + rl)*(LDK*2) + hk*16;
    const uint32_t bC = su32(s->w1c)   + (wn*32 + rl)*(LDK*2) + hk*16;

    for (int b = blockIdx.x; b < B_; b += gridDim.x) {
        __syncthreads();
        if (tid < E_) {
            s->user[tid] = user_emb[(size_t)user_ids[b] * E_ + tid];
            s->cu[tid]   = g_cu[(size_t)b * E_ + tid];
            s->c2u[tid]  = g_c2u[(size_t)b * E_ + tid];
        }
        if (tid < L_) s->ids[tid] = item_ids[b*L_ + tid];
        __syncthreads();   // ids visible for prefetch

        float4 pf[4], pi[8];
        // prefetch tile 0
        #pragma unroll
        for (int p = 0; p < 4; p++) {
            int i = tid + 256*p, r = i >> 4, q = i & 15, l = r;
            pf[p] = (l < L_) ? ((const float4*)features)[(size_t)(b*L_ + l)*16 + q]
                             : make_float4(0.f, 0.f, 0.f, 0.f);
        }
        #pragma unroll
        for (int p = 0; p < 8; p++) {
            int i = tid + 256*p, r = i >> 5, q = i & 31, l = r;
            pi[p] = (l < L_) ? ((const float4*)item_emb)[(size_t)s->ids[l]*32 + q]
                             : make_float4(0.f, 0.f, 0.f, 0.f);
        }

        for (int tile = 0; tile < 4; tile++) {
            const int base = tile * 64;
            __syncthreads();   // prior GEMM3 done reading items/comp

            // commit prefetched tile to smem (fp32 regs -> bf16)
            #pragma unroll
            for (int p = 0; p < 4; p++) {
                int i = tid + 256*p, r = i >> 4, q = i & 15;
                __nv_bfloat162* dst = (__nv_bfloat162*)(s->feat + r*LDF + q*4);
                dst[0] = __floats2bfloat162_rn(pf[p].x, pf[p].y);
                dst[1] = __floats2bfloat162_rn(pf[p].z, pf[p].w);
            }
            #pragma unroll
            for (int p = 0; p < 8; p++) {
                int i = tid + 256*p, r = i >> 5, q = i & 31;
                __nv_bfloat162* dst = (__nv_bfloat162*)(s->items + r*LDK + q*4);
                dst[0] = __floats2bfloat162_rn(pi[p].x, pi[p].y);
                dst[1] = __floats2bfloat162_rn(pi[p].z, pi[p].w);
            }
            __syncthreads();

            // prefetch tile+1 (hidden behind the 3-GEMM chain)
            if (tile < 3) {
                const int nbase = base + 64;
                #pragma unroll
                for (int p = 0; p < 4; p++) {
                    int i = tid + 256*p, r = i >> 4, q = i & 15, l = nbase + r;
                    pf[p] = (l < L_) ? ((const float4*)features)[(size_t)(b*L_ + l)*16 + q]
                                     : make_float4(0.f, 0.f, 0.f, 0.f);
                }
                #pragma unroll
                for (int p = 0; p < 8; p++) {
                    int i = tid + 256*p, r = i >> 5, q = i & 31, l = nbase + r;
                    pi[p] = (l < L_) ? ((const float4*)item_emb)[(size_t)s->ids[l]*32 + q]
                                     : make_float4(0.f, 0.f, 0.f, 0.f);
                }
            }

            float acc[2][4][4];
            // fx = relu(cu + feat @ w1f^T), K=64
            zero_acc(acc);
            gemm_lm<4>(aF, LDF*2, bF, LDF*2, acc);
            epi_store(acc, s->cu, s->fx, LDK, wm, wn, g, t4);
            __syncthreads();

            // comp = relu(fb2 + fx @ w2f^T), K=128
            zero_acc(acc);
            gemm_lm<8>(aX, LDK*2, b2f, LDK*2, acc);
            epi_store(acc, s->fb2, s->comp, LDK, wm, wn, g, t4);
            __syncthreads();

            // h = relu(c2u + items@w1i^T + comp@w1c^T); logit = w2.h + b2
            zero_acc(acc);
            gemm_lm<8>(aI, LDK*2, bI, LDK*2, acc);
            gemm_lm<8>(aC, LDK*2, bC, LDK*2, acc);
            #pragma unroll
            for (int t = 0; t < 2; t++) {
                float p0 = 0.f, p1 = 0.f;
                #pragma unroll
                for (int j = 0; j < 4; j++) {
                    const int c = wn*32 + j*8 + t4*2;
                    const float a0 = s->c2u[c], a1 = s->c2u[c+1];
                    const float q0 = s->w2v[c], q1 = s->w2v[c+1];
                    p0 += fmaxf(acc[t][j][0] + a0, 0.f)*q0 + fmaxf(acc[t][j][1] + a1, 0.f)*q1;
                    p1 += fmaxf(acc[t][j][2] + a0, 0.f)*q0 + fmaxf(acc[t][j][3] + a1, 0.f)*q1;
                }
                p0 += __shfl_xor_sync(0xffffffffu, p0, 1);
                p0 += __shfl_xor_sync(0xffffffffu, p0, 2);
                p1 += __shfl_xor_sync(0xffffffffu, p1, 1);
                p1 += __shfl_xor_sync(0xffffffffu, p1, 2);
                if (t4 == 0) {
                    const int r = wm*32 + t*16 + g;
                    s->part[wn][r]     = p0;
                    s->part[wn][r + 8] = p1;
                }
            }
            __syncthreads();
            if (tid < 64)
                s->logits[base + tid] = b2v + s->part[0][tid] + s->part[1][tid]
                                            + s->part[2][tid] + s->part[3][tid];
        }
        __syncthreads();

        float mv = -3.4e38f;
        for (int i = tid; i < L_; i += 256) mv = fmaxf(mv, s->logits[i]);
        mv = block_reduce(mv, true, s, tid);
        float sv = 0.f;
        for (int i = tid; i < L_; i += 256) {
            float e = __expf(s->logits[i] - mv);
            s->logits[i] = e;
            sv += e;
        }
        sv = block_reduce(sv, false, s, tid);
        const float inv = 1.f / sv;

        const int e = tid & 127, half = tid >> 7;
        float accv = 0.f;
        for (int l = half; l < L_; l += 2)
            accv += s->logits[l] * __ldg(item_emb + (size_t)s->ids[l]*E_ + e);
        float* pbuf = &s->part[0][0];
        if (half) pbuf[e] = accv;
        __syncthreads();
        if (!half)
            out[(size_t)b*E_ + e] = s->user[e] + (accv + pbuf[e]) * inv;
    }
}

extern "C" void kernel_launch(void* const* d_in, const int* in_sizes, int n_in,
                              void* d_out, int out_size) {
    const int*   user_ids = (const int*)d_in[0];
    const int*   item_ids = (const int*)d_in[1];
    const float* features = (const float*)d_in[2];
    const float* user_emb = (const float*)d_in[3];
    const float* item_emb = (const float*)d_in[4];
    const float* feat_w1  = (const float*)d_in[5];
    const float* feat_b1  = (const float*)d_in[6];
    const float* feat_w2  = (const float*)d_in[7];
    const float* feat_b2  = (const float*)d_in[8];
    const float* w1       = (const float*)d_in[9];
    const float* b1       = (const float*)d_in[10];
    const float* w2       = (const float*)d_in[11];
    const float* b2       = (const float*)d_in[12];
    float* out = (float*)d_out;

    cudaFuncSetAttribute(prep_user, cudaFuncAttributeMaxDynamicSharedMemorySize, PREP_SMEM);
    cudaFuncSetAttribute(main_kernel, cudaFuncAttributeMaxDynamicSharedMemorySize,
                         (int)sizeof(SmemMain));
    int nsm = 148;
    cudaDeviceGetAttribute(&nsm, cudaDevAttrMultiProcessorCount, 0);

    prep_user<<<128, 256, PREP_SMEM>>>(user_ids, user_emb, feat_w1, feat_w2, w1,
                                       feat_b1, b1);
    main_kernel<<<nsm, 256, sizeof(SmemMain)>>>(user_ids, item_ids, features, user_emb,
                                                item_emb, feat_b2, w2, b2, out);
}